// round 3
// baseline (speedup 1.0000x reference)
#include <cuda_runtime.h>
#include <cuda_bf16.h>
#include <math.h>
#include <stdint.h>

#define BB 4
#define DD 256
#define LL 4096
#define NN (BB*LL)      // 16384 tokens
#define KK 8192
#define EPSF 1e-12f
#define MARGIN 4e-3f
#define NCAND 24

// ---- GEMM tiling: block = 128 tokens x full K, chunks of 128 codes ----
#define GLD 264                      // halves per smem row (528B, 16B-aligned)
#define GTILE_HALVES (128*GLD)
#define GTILE_BYTES (GTILE_HALVES*2) // 67584
#define GSMEM (3*GTILE_BYTES)        // A + 2x B = 202752 bytes

// ---- device scratch ----
__device__ float          g_cbn[KK*DD];     // normalized codebook fp32 (8 MB)
__device__ float          g_xn[NN*DD];      // normalized tokens fp32 (16 MB)
__device__ __nv_bfloat16  g_ch[KK*DD];      // normalized codebook bf16 (4 MB)
__device__ __nv_bfloat16  g_xh[NN*DD];      // normalized tokens bf16 (8 MB)
__device__ float          g_norm[NN];
__device__ float          g_candv[NN*NCAND];
__device__ int            g_candi[NN*NCAND];
__device__ double         g_acc;

// ------------------------------------------------------------------
__global__ void init_acc_kernel() { g_acc = 0.0; }

__device__ __forceinline__ uint32_t pack_bf16x2(float lo, float hi) {
    uint32_t r;
    asm("cvt.rn.bf16x2.f32 %0, %1, %2;" : "=r"(r) : "f"(hi), "f"(lo));
    return r;
}

// one warp per codebook row: cn = c / max(||c||, eps); fp32 + bf16 outputs
__global__ void normalize_codebook_kernel(const float* __restrict__ cb) {
    int row  = blockIdx.x * 8 + (threadIdx.x >> 5);
    int lane = threadIdx.x & 31;
    const float4* src = (const float4*)(cb + (size_t)row * DD);
    float4 v0 = src[lane];
    float4 v1 = src[lane + 32];
    float ss = v0.x*v0.x + v0.y*v0.y + v0.z*v0.z + v0.w*v0.w
             + v1.x*v1.x + v1.y*v1.y + v1.z*v1.z + v1.w*v1.w;
    #pragma unroll
    for (int o = 16; o; o >>= 1) ss += __shfl_xor_sync(~0u, ss, o);
    float inv = 1.0f / fmaxf(sqrtf(ss), EPSF);
    v0.x*=inv; v0.y*=inv; v0.z*=inv; v0.w*=inv;
    v1.x*=inv; v1.y*=inv; v1.z*=inv; v1.w*=inv;
    float4* dst = (float4*)(g_cbn + (size_t)row * DD);
    dst[lane] = v0; dst[lane + 32] = v1;
    uint2* hd = (uint2*)(g_ch + (size_t)row * DD);
    hd[lane]      = make_uint2(pack_bf16x2(v0.x, v0.y), pack_bf16x2(v0.z, v0.w));
    hd[lane + 32] = make_uint2(pack_bf16x2(v1.x, v1.y), pack_bf16x2(v1.z, v1.w));
}

// fused: transpose [B,D,L] tile -> norms -> xn fp32 + bf16 (single x read)
__global__ void make_xn_kernel(const float* __restrict__ x) {
    __shared__ float tile[32][261];   // [l][d], stride 261 (odd*?) conflict-free
    int b = blockIdx.y, l0 = blockIdx.x * 32;
    int tid = threadIdx.x, wid = tid >> 5, lane = tid & 31;
    // load: warp w reads d rows [w*32, w*32+32)
    #pragma unroll
    for (int j = 0; j < 32; j++) {
        int d = wid * 32 + j;
        tile[lane][d] = x[(size_t)b * DD * LL + (size_t)d * LL + l0 + lane];
    }
    __syncthreads();
    // warp w handles tokens w*4 .. w*4+3
    #pragma unroll
    for (int i = 0; i < 4; i++) {
        int t = wid * 4 + i;
        int n = b * LL + l0 + t;
        float ss = 0.0f;
        #pragma unroll
        for (int j = 0; j < 8; j++) { float v = tile[t][lane + 32*j]; ss = fmaf(v, v, ss); }
        #pragma unroll
        for (int o = 16; o; o >>= 1) ss += __shfl_xor_sync(~0u, ss, o);
        float nrm = fmaxf(sqrtf(ss), EPSF);
        float inv = 1.0f / nrm;
        if (lane == 0) g_norm[n] = nrm;
        #pragma unroll
        for (int j = 0; j < 8; j++) {
            int d = lane + 32*j;
            float v = tile[t][d] * inv;
            g_xn[(size_t)n * DD + d] = v;
            g_xh[(size_t)n * DD + d] = __float2bfloat16(v);
        }
    }
}

// ------------------------------------------------------------------
#define CP_ASYNC16(dst, src) \
    asm volatile("cp.async.cg.shared.global [%0], [%1], 16;\n" :: "r"(dst), "l"(src))

__device__ __forceinline__ void load_a(uint32_t sbase, int mbase, int tid) {
    #pragma unroll
    for (int i = 0; i < 16; i++) {
        int id = tid + 256 * i;
        int row = id >> 5, off = (id & 31) * 16;
        CP_ASYNC16(sbase + row * 528 + off,
                   (const char*)g_xh + (size_t)(mbase + row) * 512 + off);
    }
}
__device__ __forceinline__ void load_b(uint32_t sbase, int kc, int buf, int tid) {
    #pragma unroll
    for (int i = 0; i < 16; i++) {
        int id = tid + 256 * i;
        int row = id >> 5, off = (id & 31) * 16;
        CP_ASYNC16(sbase + (1 + buf) * GTILE_BYTES + row * 528 + off,
                   (const char*)g_ch + (size_t)(kc * 128 + row) * 512 + off);
    }
}

// fused bf16 MMA GEMM + per-row top-3 candidate tracking (fp32 accum).
// block = 128 tokens x K=8192 (64 chunks of 128 codes).
__global__ void __launch_bounds__(256, 1) gemm_argmax_kernel() {
    extern __shared__ __nv_bfloat16 sm[];
    uint32_t sbase = (uint32_t)__cvta_generic_to_shared(sm);
    int tid = threadIdx.x;
    int wid = tid >> 5, lane = tid & 31;
    int warp_m = wid & 3, warp_n = wid >> 2;     // 4x2 warps: 32 rows x 64 cols
    int grp = lane >> 2, qid = lane & 3;
    int mbase = blockIdx.x * 128;

    load_a(sbase, mbase, tid);
    asm volatile("cp.async.commit_group;\n" ::);
    load_b(sbase, 0, 0, tid);
    asm volatile("cp.async.commit_group;\n" ::);

    // per-thread top-3 for each of 4 row-slots
    float v1[4], v2[4], v3[4]; int i1[4], i2[4], i3[4];
    #pragma unroll
    for (int s = 0; s < 4; s++) {
        v1[s] = v2[s] = v3[s] = -2.0f;
        i1[s] = i2[s] = i3[s] = 0x7fffffff;
    }

    for (int kc = 0; kc < KK / 128; kc++) {
        if (kc < KK / 128 - 1) {
            load_b(sbase, kc + 1, (kc + 1) & 1, tid);
            asm volatile("cp.async.commit_group;\n" ::);
            asm volatile("cp.async.wait_group 1;\n" ::);
        } else {
            asm volatile("cp.async.wait_group 0;\n" ::);
        }
        __syncthreads();

        float c[2][8][4];
        #pragma unroll
        for (int mi = 0; mi < 2; mi++)
            #pragma unroll
            for (int ni = 0; ni < 8; ni++)
                #pragma unroll
                for (int j = 0; j < 4; j++) c[mi][ni][j] = 0.0f;

        const __nv_bfloat16* sA = sm;
        const __nv_bfloat16* sB = sm + (1 + (kc & 1)) * GTILE_HALVES;
        #pragma unroll
        for (int ks = 0; ks < DD; ks += 16) {
            uint32_t a[2][4], b[8][2];
            #pragma unroll
            for (int mi = 0; mi < 2; mi++) {
                const __nv_bfloat16* pa = sA + (warp_m*32 + mi*16 + grp) * GLD + ks + qid*2;
                a[mi][0] = *(const uint32_t*)(pa);
                a[mi][1] = *(const uint32_t*)(pa + 8*GLD);
                a[mi][2] = *(const uint32_t*)(pa + 8);
                a[mi][3] = *(const uint32_t*)(pa + 8*GLD + 8);
            }
            #pragma unroll
            for (int ni = 0; ni < 8; ni++) {
                const __nv_bfloat16* pb = sB + (warp_n*64 + ni*8 + grp) * GLD + ks + qid*2;
                b[ni][0] = *(const uint32_t*)(pb);
                b[ni][1] = *(const uint32_t*)(pb + 8);
            }
            #pragma unroll
            for (int mi = 0; mi < 2; mi++)
                #pragma unroll
                for (int ni = 0; ni < 8; ni++)
                    asm volatile(
                        "mma.sync.aligned.m16n8k16.row.col.f32.bf16.bf16.f32 "
                        "{%0,%1,%2,%3}, {%4,%5,%6,%7}, {%8,%9}, {%0,%1,%2,%3};\n"
                        : "+f"(c[mi][ni][0]), "+f"(c[mi][ni][1]),
                          "+f"(c[mi][ni][2]), "+f"(c[mi][ni][3])
                        : "r"(a[mi][0]), "r"(a[mi][1]), "r"(a[mi][2]), "r"(a[mi][3]),
                          "r"(b[ni][0]), "r"(b[ni][1]));
        }

        // chunk epilogue: update running top-3 per row-slot (fast-path guarded)
        #pragma unroll
        for (int s = 0; s < 4; s++) {
            int mi = s >> 1, h = s & 1;
            float m0 = -2.0f;
            #pragma unroll
            for (int ni = 0; ni < 8; ni++)
                m0 = fmaxf(m0, fmaxf(c[mi][ni][h*2], c[mi][ni][h*2+1]));
            if (m0 > v3[s]) {
                #pragma unroll
                for (int ni = 0; ni < 8; ni++)
                    #pragma unroll
                    for (int j = 0; j < 2; j++) {
                        float v = c[mi][ni][h*2 + j];
                        int col = kc*128 + warp_n*64 + ni*8 + qid*2 + j;
                        if (v > v1[s]) {
                            v3[s]=v2[s]; i3[s]=i2[s];
                            v2[s]=v1[s]; i2[s]=i1[s];
                            v1[s]=v;     i1[s]=col;
                        } else if (v > v2[s]) {
                            v3[s]=v2[s]; i3[s]=i2[s];
                            v2[s]=v;     i2[s]=col;
                        } else if (v > v3[s]) {
                            v3[s]=v;     i3[s]=col;
                        }
                    }
            }
        }
        __syncthreads();   // all reads of this buffer done before refill
    }

    // write candidates: per row, 8 threads x 3 = 24 slots
    #pragma unroll
    for (int s = 0; s < 4; s++) {
        int row = mbase + warp_m*32 + (s>>1)*16 + (s&1)*8 + grp;
        int base = row * NCAND + (warp_n*4 + qid) * 3;
        g_candv[base+0] = v1[s]; g_candi[base+0] = i1[s];
        g_candv[base+1] = v2[s]; g_candi[base+1] = i2[s];
        g_candv[base+2] = v3[s]; g_candi[base+2] = i3[s];
    }
}

// ------------------------------------------------------------------
// fused: exact fp32 rescore of candidates -> rotation trick -> commit loss
// -> transposed write to out [B,D,L].  block = 32 tokens, warp = 4 tokens.
__global__ void rotate_out_kernel(float* __restrict__ out) {
    __shared__ float tile[256][33];   // [d][token]
    int b = blockIdx.y, l0 = blockIdx.x * 32;
    int tid = threadIdx.x, wid = tid >> 5, lane = tid & 31;

    #pragma unroll
    for (int i = 0; i < 4; i++) {
        int t = wid * 4 + i;
        int n = b * LL + l0 + t;

        // candidates + threshold
        float cv = (lane < NCAND) ? g_candv[n*NCAND + lane] : -3.0f;
        int   ck = (lane < NCAND) ? g_candi[n*NCAND + lane] : 0x7fffffff;
        float rmax = cv;
        #pragma unroll
        for (int o = 16; o; o >>= 1) rmax = fmaxf(rmax, __shfl_xor_sync(~0u, rmax, o));
        float thr = rmax - MARGIN;

        // exact fp32 rescore (same summation as prior passing rounds)
        const float4* xp = (const float4*)(g_xn + (size_t)n * DD);
        float4 xa0 = xp[lane*2], xa1 = xp[lane*2 + 1];
        float bestv = -3.0f; int besti = 0x7fffffff;
        for (int ci = 0; ci < NCAND; ci++) {
            float v = __shfl_sync(~0u, cv, ci);
            int   k = __shfl_sync(~0u, ck, ci);
            if (v >= thr) {
                const float4* cp = (const float4*)(g_cbn + (size_t)k * DD);
                float4 c0 = cp[lane*2], c1 = cp[lane*2 + 1];
                float d = xa0.x*c0.x + xa0.y*c0.y + xa0.z*c0.z + xa0.w*c0.w
                        + xa1.x*c1.x + xa1.y*c1.y + xa1.z*c1.z + xa1.w*c1.w;
                #pragma unroll
                for (int o = 16; o; o >>= 1) d += __shfl_xor_sync(~0u, d, o);
                if (d > bestv || (d == bestv && k < besti)) { bestv = d; besti = k; }
            }
        }

        // rotation trick
        float nrm = g_norm[n];
        const float4* qp = (const float4*)(g_cbn + (size_t)besti * DD);
        float4 x0 = xp[lane], x1 = xp[lane + 32];
        float4 q0 = qp[lane], q1 = qp[lane + 32];
        float s0x = x0.x + q0.x, s0y = x0.y + q0.y, s0z = x0.z + q0.z, s0w = x0.w + q0.w;
        float s1x = x1.x + q1.x, s1y = x1.y + q1.y, s1z = x1.z + q1.z, s1w = x1.w + q1.w;
        float ss = s0x*s0x + s0y*s0y + s0z*s0z + s0w*s0w
                 + s1x*s1x + s1y*s1y + s1z*s1z + s1w*s1w;
        float xs = x0.x*s0x + x0.y*s0y + x0.z*s0z + x0.w*s0w
                 + x1.x*s1x + x1.y*s1y + x1.z*s1z + x1.w*s1w;
        #pragma unroll
        for (int o = 16; o; o >>= 1) {
            ss += __shfl_xor_sync(~0u, ss, o);
            xs += __shfl_xor_sync(~0u, xs, o);
        }
        float sn = fmaxf(sqrtf(ss), EPSF);
        float cc = 2.0f * (xs / sn) / sn;

        float4 r0, r1;
        r0.x = x0.x - cc*s0x + 2.0f*q0.x;  r0.y = x0.y - cc*s0y + 2.0f*q0.y;
        r0.z = x0.z - cc*s0z + 2.0f*q0.z;  r0.w = x0.w - cc*s0w + 2.0f*q0.w;
        r1.x = x1.x - cc*s1x + 2.0f*q1.x;  r1.y = x1.y - cc*s1y + 2.0f*q1.y;
        r1.z = x1.z - cc*s1z + 2.0f*q1.z;  r1.w = x1.w - cc*s1w + 2.0f*q1.w;

        int d0 = lane * 4;
        tile[d0+0][t] = r0.x; tile[d0+1][t] = r0.y; tile[d0+2][t] = r0.z; tile[d0+3][t] = r0.w;
        tile[128+d0+0][t] = r1.x; tile[128+d0+1][t] = r1.y;
        tile[128+d0+2][t] = r1.z; tile[128+d0+3][t] = r1.w;

        // commit loss: sum (rot - xn*norm)^2
        float d0x = r0.x - x0.x*nrm, d0y = r0.y - x0.y*nrm, d0z = r0.z - x0.z*nrm, d0w = r0.w - x0.w*nrm;
        float d1x = r1.x - x1.x*nrm, d1y = r1.y - x1.y*nrm, d1z = r1.z - x1.z*nrm, d1w = r1.w - x1.w*nrm;
        float cs = d0x*d0x + d0y*d0y + d0z*d0z + d0w*d0w
                 + d1x*d1x + d1y*d1y + d1z*d1z + d1w*d1w;
        #pragma unroll
        for (int o = 16; o; o >>= 1) cs += __shfl_xor_sync(~0u, cs, o);
        if (lane == 0) atomicAdd(&g_acc, (double)cs);
    }
    __syncthreads();

    // coalesced transposed write: warp w writes d rows [w*32, w*32+32)
    #pragma unroll
    for (int j = 0; j < 32; j++) {
        int d = wid * 32 + j;
        out[(size_t)b * DD * LL + (size_t)d * LL + l0 + lane] = tile[d][lane];
    }
}

__global__ void finalize_kernel(float* __restrict__ out, int out_size) {
    long q = (long)BB * DD * LL;
    float loss = (float)(0.25 * g_acc / (double)((long)NN * DD));
    for (long i = q + threadIdx.x; i < (long)out_size; i += blockDim.x) out[i] = loss;
}

// ------------------------------------------------------------------
extern "C" void kernel_launch(void* const* d_in, const int* in_sizes, int n_in,
                              void* d_out, int out_size) {
    const float* x  = (const float*)d_in[0];   // [4,256,4096]
    const float* cb = (const float*)d_in[1];   // [8192,256]
    float* out = (float*)d_out;

    static int attr_set = 0;
    if (!attr_set) {
        cudaFuncSetAttribute(gemm_argmax_kernel,
                             cudaFuncAttributeMaxDynamicSharedMemorySize, GSMEM);
        attr_set = 1;
    }

    init_acc_kernel<<<1, 1>>>();
    normalize_codebook_kernel<<<KK / 8, 256>>>(cb);
    make_xn_kernel<<<dim3(LL / 32, BB), 256>>>(x);
    gemm_argmax_kernel<<<NN / 128, 256, GSMEM>>>();
    rotate_out_kernel<<<dim3(LL / 32, BB), 256>>>(out);
    finalize_kernel<<<1, 256>>>(out, out_size);
}